// round 9
// baseline (speedup 1.0000x reference)
#include <cuda_runtime.h>
#include <cstdint>

#define BH      16
#define LSEQ    4096
#define DIM     128
#define CHK     32
#define DV      16
#define NSLICE  8
#define NCHUNK  (LSEQ / CHK)
#define PD      132   // padded row length (floats), 528B, 16B-aligned
#define ATP     36    // Atb/UAT padded stride
#define THR2    512

typedef unsigned long long ull;

// ---- scratch (device globals; allocation-free) ----
__device__ float g_QN[(size_t)BH * LSEQ * DIM];
__device__ float g_KN[(size_t)BH * LSEQ * DIM];
__device__ float g_W [(size_t)BH * LSEQ * DIM];
__device__ float g_U [(size_t)BH * LSEQ * DIM];
__device__ float g_AT[(size_t)BH * NCHUNK * CHK * CHK];

// ---- packed f32x2 helpers ----
__device__ __forceinline__ ull ffma2(ull a, ull b, ull c) {
    ull d;
    asm("fma.rn.f32x2 %0, %1, %2, %3;" : "=l"(d) : "l"(a), "l"(b), "l"(c));
    return d;
}
__device__ __forceinline__ ull fadd2(ull a, ull b) {
    ull d;
    asm("add.rn.f32x2 %0, %1, %2;" : "=l"(d) : "l"(a), "l"(b));
    return d;
}
__device__ __forceinline__ ull pack2(float v) {
    ull d;
    asm("mov.b64 %0, {%1, %1};" : "=l"(d) : "f"(v));
    return d;
}
__device__ __forceinline__ float hadd2(ull v) {
    float lo, hi;
    asm("mov.b64 {%0, %1}, %2;" : "=f"(lo), "=f"(hi) : "l"(v));
    return lo + hi;
}

// ---- cp.async helpers ----
__device__ __forceinline__ void cp16(void* smem_dst, const void* gmem_src) {
    uint32_t s = (uint32_t)__cvta_generic_to_shared(smem_dst);
    asm volatile("cp.async.cg.shared.global [%0], [%1], 16;\n" :: "r"(s), "l"(gmem_src));
}
__device__ __forceinline__ void cp_commit() {
    asm volatile("cp.async.commit_group;\n" ::: "memory");
}
__device__ __forceinline__ void cp_wait_all() {
    asm volatile("cp.async.wait_group 0;\n" ::: "memory");
}

// ============================================================
// Kernel 1: per-(bh,chunk) prep; register-resident load+norm+scale
// ============================================================
struct SM1 {
    float Qn[CHK][PD];
    float Kn[CHK][PD];
    float Kb[CHK][PD];
    float Vb[CHK][PD];
    float T [CHK][CHK + 1];
};

extern "C" __global__ void __launch_bounds__(256)
k1_prepare(const float* __restrict__ q, const float* __restrict__ k,
           const float* __restrict__ v, const float* __restrict__ beta)
{
    extern __shared__ __align__(16) char smraw1[];
    SM1& sm = *reinterpret_cast<SM1*>(smraw1);
    const int ch = blockIdx.x, bh = blockIdx.y;
    const int tid = threadIdx.x;
    const size_t base = ((size_t)bh * LSEQ + (size_t)ch * CHK) * DIM;

    // ---- fused load + norm + scale: row r owned by 8 lanes ----
    {
        const int r = tid >> 3, sub = tid & 7;      // 32 rows x 8 subs
        const float* qr = q + base + (size_t)r * DIM + sub * 16;
        const float* kr = k + base + (size_t)r * DIM + sub * 16;
        const float* vr = v + base + (size_t)r * DIM + sub * 16;
        float4 qv[4], kv[4], vv[4];
        #pragma unroll
        for (int g = 0; g < 4; g++) {
            qv[g] = *(const float4*)(qr + g * 4);
            kv[g] = *(const float4*)(kr + g * 4);
            vv[g] = *(const float4*)(vr + g * 4);
        }
        float sq = 0.f, sk = 0.f;
        #pragma unroll
        for (int g = 0; g < 4; g++) {
            sq += qv[g].x*qv[g].x + qv[g].y*qv[g].y + qv[g].z*qv[g].z + qv[g].w*qv[g].w;
            sk += kv[g].x*kv[g].x + kv[g].y*kv[g].y + kv[g].z*kv[g].z + kv[g].w*kv[g].w;
        }
        #pragma unroll
        for (int m = 4; m >= 1; m >>= 1) {
            sq += __shfl_xor_sync(0xffffffffu, sq, m);
            sk += __shfl_xor_sync(0xffffffffu, sk, m);
        }
        const float rq = rsqrtf(sq), rk = rsqrtf(sk);
        const float bt = beta[(size_t)bh * LSEQ + ch * CHK + r];

        float* gq = g_QN + base + (size_t)r * DIM + sub * 16;
        float* gk = g_KN + base + (size_t)r * DIM + sub * 16;
        #pragma unroll
        for (int g = 0; g < 4; g++) {
            float4 qn, kn, kb, vb;
            qn.x = qv[g].x*rq; qn.y = qv[g].y*rq; qn.z = qv[g].z*rq; qn.w = qv[g].w*rq;
            kn.x = kv[g].x*rk; kn.y = kv[g].y*rk; kn.z = kv[g].z*rk; kn.w = kv[g].w*rk;
            kb.x = kn.x*bt; kb.y = kn.y*bt; kb.z = kn.z*bt; kb.w = kn.w*bt;
            vb.x = vv[g].x*bt; vb.y = vv[g].y*bt; vb.z = vv[g].z*bt; vb.w = vv[g].w*bt;
            const int c = sub * 16 + g * 4;
            *(float4*)&sm.Qn[r][c] = qn;
            *(float4*)&sm.Kn[r][c] = kn;
            *(float4*)&sm.Kb[r][c] = kb;
            *(float4*)&sm.Vb[r][c] = vb;
            *(float4*)(gq + g * 4) = qn;
            *(float4*)(gk + g * 4) = kn;
        }
    }
    __syncthreads();

    { // T (strict lower, kb.kn) and At (causal, qn.kn), 2x2 tiles, f32x2 math
        int a = tid >> 4, b = tid & 15;
        int i0 = 2 * a, j0 = 2 * b;
        ull t00 = 0, t01 = 0, t10 = 0, t11 = 0;
        ull a00 = 0, a01 = 0, a10 = 0, a11 = 0;
        #pragma unroll 8
        for (int c4 = 0; c4 < DIM; c4 += 4) {
            ulonglong2 kb0 = *(const ulonglong2*)&sm.Kb[i0][c4];
            ulonglong2 kb1 = *(const ulonglong2*)&sm.Kb[i0 + 1][c4];
            ulonglong2 qn0 = *(const ulonglong2*)&sm.Qn[i0][c4];
            ulonglong2 qn1 = *(const ulonglong2*)&sm.Qn[i0 + 1][c4];
            ulonglong2 kn0 = *(const ulonglong2*)&sm.Kn[j0][c4];
            ulonglong2 kn1 = *(const ulonglong2*)&sm.Kn[j0 + 1][c4];
            t00 = ffma2(kb0.x, kn0.x, t00); t00 = ffma2(kb0.y, kn0.y, t00);
            t01 = ffma2(kb0.x, kn1.x, t01); t01 = ffma2(kb0.y, kn1.y, t01);
            t10 = ffma2(kb1.x, kn0.x, t10); t10 = ffma2(kb1.y, kn0.y, t10);
            t11 = ffma2(kb1.x, kn1.x, t11); t11 = ffma2(kb1.y, kn1.y, t11);
            a00 = ffma2(qn0.x, kn0.x, a00); a00 = ffma2(qn0.y, kn0.y, a00);
            a01 = ffma2(qn0.x, kn1.x, a01); a01 = ffma2(qn0.y, kn1.y, a01);
            a10 = ffma2(qn1.x, kn0.x, a10); a10 = ffma2(qn1.y, kn0.y, a10);
            a11 = ffma2(qn1.x, kn1.x, a11); a11 = ffma2(qn1.y, kn1.y, a11);
        }
        sm.T[i0][j0]         = (i0 > j0)         ? hadd2(t00) : 0.f;
        sm.T[i0][j0 + 1]     = (i0 > j0 + 1)     ? hadd2(t01) : 0.f;
        sm.T[i0 + 1][j0]     = (i0 + 1 > j0)     ? hadd2(t10) : 0.f;
        sm.T[i0 + 1][j0 + 1] = (i0 + 1 > j0 + 1) ? hadd2(t11) : 0.f;
        float* atg = g_AT + (size_t)(bh * NCHUNK + ch) * CHK * CHK;
        atg[i0 * CHK + j0]           = (i0 >= j0)         ? hadd2(a00) : 0.f;
        atg[i0 * CHK + j0 + 1]       = (i0 >= j0 + 1)     ? hadd2(a01) : 0.f;
        atg[(i0 + 1) * CHK + j0]     = (i0 + 1 >= j0)     ? hadd2(a10) : 0.f;
        atg[(i0 + 1) * CHK + j0 + 1] = (i0 + 1 >= j0 + 1) ? hadd2(a11) : 0.f;
    }
    __syncthreads();

    { // forward substitution: 256 threads = 256 rhs columns [kb | vb]
        const bool left = tid < DIM;
        const int col = left ? tid : tid - DIM;
        float x[CHK];
        #pragma unroll
        for (int i = 0; i < CHK; i++) x[i] = left ? sm.Kb[i][col] : sm.Vb[i][col];
        #pragma unroll
        for (int i = 1; i < CHK; i++) {
            float acc = x[i];
            #pragma unroll
            for (int m = 0; m < i; m++) acc -= sm.T[i][m] * x[m];
            x[i] = acc;
        }
        float* dst = (left ? g_W : g_U) + base + col;
        #pragma unroll
        for (int i = 0; i < CHK; i++) dst[(size_t)i * DIM] = x[i];
    }
}

// ============================================================
// Kernel 2: sequential scan; A on warps 0-7 (4i x 4j tiles),
//           C1 (warps 4-15) || C2 (warps 0-3)
// ============================================================
struct Buf {
    float Qn [CHK][PD];
    float Kn [CHK][PD];
    float Wv [CHK][PD];
    float Ub [CHK][DV];
    float Atb[CHK][ATP];
};
struct SM2 {
    float St  [DV][PD];     // S^T slice: [j][c]
    float UAT [DV][ATP];    // (u - w@S)^T: [j][i]
    float Obuf[CHK][17];    // q@S partials
    Buf   buf[2];
};

__device__ __forceinline__ void load_buf(Buf& B, int bh, int ch, int sl, int tid)
{
    const size_t base = ((size_t)bh * LSEQ + (size_t)ch * CHK) * DIM;
    const float* qs  = g_QN + base;
    const float* ks  = g_KN + base;
    const float* ws  = g_W  + base;
    const float* us  = g_U  + base + sl * DV;
    const float* ats = g_AT + (size_t)(bh * NCHUNK + ch) * CHK * CHK;

    #pragma unroll
    for (int t = tid; t < 1024; t += THR2) {
        int r = t >> 5, c4 = (t & 31) * 4;
        cp16(&B.Qn[r][c4], qs + r * DIM + c4);
        cp16(&B.Kn[r][c4], ks + r * DIM + c4);
        cp16(&B.Wv[r][c4], ws + r * DIM + c4);
    }
    if (tid < 128) {
        int r = tid >> 2, c4 = (tid & 3) * 4;
        cp16(&B.Ub[r][c4], us + r * DIM + c4);
    }
    if (tid < 256) {
        int r = tid >> 3, c4 = (tid & 7) * 4;
        cp16(&B.Atb[r][c4], ats + r * CHK + c4);
    }
}

extern "C" __global__ void __launch_bounds__(THR2, 1)
k2_scan(float* __restrict__ out, float* __restrict__ sfinal, int write_s)
{
    extern __shared__ __align__(16) char smraw2[];
    SM2& sm = *reinterpret_cast<SM2*>(smraw2);
    const int bh = blockIdx.x, sl = blockIdx.y;
    const int tid = threadIdx.x;
    const int warp = tid >> 5, lane = tid & 31;

    float* ob = out + (size_t)bh * LSEQ * DIM + sl * DV;

    for (int idx = tid; idx < DV * DIM; idx += THR2)
        sm.St[idx >> 7][idx & 127] = 0.f;

    load_buf(sm.buf[0], bh, 0, sl, tid);
    cp_commit();

    // phase A (warps 0..7): 32 tiles (8 i-groups x 4 j-groups), 8-way c-split
    const int csplit = lane & 7;
    const int tileA  = warp * 4 + (lane >> 3);   // 0..31 for warp<8
    const int ia0 = (tileA & 7) * 4;
    const int ja0 = (tileA >> 3) * 4;

    // C2 ownership (warps 0..3): warp w -> js rows {w, w+4, w+8, w+12}
    const int c0 = lane * 4;

    for (int ch = 0; ch < NCHUNK; ch++) {
        cp_wait_all();
        __syncthreads();
        if (ch + 1 < NCHUNK) {
            load_buf(sm.buf[(ch + 1) & 1], bh, ch + 1, sl, tid);
            cp_commit();
        }
        const Buf& B = sm.buf[ch & 1];

        // ---- phase A: O = qn@S, A = w@S; 4i x 4j tile, 8-way c-split ----
        if (warp < 8) {
            ull O2[4][4] = {}, A2[4][4] = {};
            #pragma unroll
            for (int cc = 0; cc < 4; cc++) {
                const int c4 = csplit * 16 + cc * 4;
                ulonglong2 qv[4], wv[4];
                #pragma unroll
                for (int ii = 0; ii < 4; ii++) {
                    qv[ii] = *(const ulonglong2*)&B.Qn[ia0 + ii][c4];
                    wv[ii] = *(const ulonglong2*)&B.Wv[ia0 + ii][c4];
                }
                #pragma unroll
                for (int jj = 0; jj < 4; jj++) {
                    ulonglong2 s = *(const ulonglong2*)&sm.St[ja0 + jj][c4];
                    #pragma unroll
                    for (int ii = 0; ii < 4; ii++) {
                        O2[ii][jj] = ffma2(qv[ii].x, s.x, O2[ii][jj]);
                        O2[ii][jj] = ffma2(qv[ii].y, s.y, O2[ii][jj]);
                        A2[ii][jj] = ffma2(wv[ii].x, s.x, A2[ii][jj]);
                        A2[ii][jj] = ffma2(wv[ii].y, s.y, A2[ii][jj]);
                    }
                }
            }
            float Ov[4][4], Av[4][4];
            #pragma unroll
            for (int ii = 0; ii < 4; ii++)
                #pragma unroll
                for (int jj = 0; jj < 4; jj++) {
                    Ov[ii][jj] = hadd2(O2[ii][jj]);
                    Av[ii][jj] = hadd2(A2[ii][jj]);
                }
            #pragma unroll
            for (int m = 4; m >= 1; m >>= 1) {
                #pragma unroll
                for (int ii = 0; ii < 4; ii++)
                    #pragma unroll
                    for (int jj = 0; jj < 4; jj++) {
                        Ov[ii][jj] += __shfl_xor_sync(0xffffffffu, Ov[ii][jj], m);
                        Av[ii][jj] += __shfl_xor_sync(0xffffffffu, Av[ii][jj], m);
                    }
            }
            if (csplit == 0) {
                #pragma unroll
                for (int ii = 0; ii < 4; ii++)
                    #pragma unroll
                    for (int jj = 0; jj < 4; jj++) {
                        sm.UAT[ja0 + jj][ia0 + ii] =
                            B.Ub[ia0 + ii][ja0 + jj] - Av[ii][jj];
                        sm.Obuf[ia0 + ii][ja0 + jj] = Ov[ii][jj];
                    }
            }
        }
        __syncthreads();

        if (warp >= 4) {
            // ---- C1 (warps 4..15): out = Obuf + At @ UA, strided cells ----
            #pragma unroll 2
            for (int cell = tid - 128; cell < CHK * DV; cell += 384) {
                const int i1 = cell >> 4, j1 = cell & 15;
                ull o2 = 0;
                #pragma unroll
                for (int f4 = 0; f4 < CHK; f4 += 4) {
                    ulonglong2 a2v = *(const ulonglong2*)&B.Atb[i1][f4];
                    ulonglong2 u2v = *(const ulonglong2*)&sm.UAT[j1][f4];
                    o2 = ffma2(a2v.x, u2v.x, o2);
                    o2 = ffma2(a2v.y, u2v.y, o2);
                }
                ob[(size_t)(ch * CHK + i1) * DIM + j1] = sm.Obuf[i1][j1] + hadd2(o2);
            }
        } else {
            // ---- C2 (warps 0..3): St[js][c0..3] += sum_r UA[r][js]*kn[r][c] ----
            ull acc[4][2] = {};
            #pragma unroll
            for (int r0 = 0; r0 < CHK; r0 += 4) {
                float4 u0 = *(const float4*)&sm.UAT[warp     ][r0];
                float4 u1 = *(const float4*)&sm.UAT[warp + 4 ][r0];
                float4 u2 = *(const float4*)&sm.UAT[warp + 8 ][r0];
                float4 u3 = *(const float4*)&sm.UAT[warp + 12][r0];
                #pragma unroll
                for (int rr = 0; rr < 4; rr++) {
                    ulonglong2 kv = *(const ulonglong2*)&B.Kn[r0 + rr][c0];
                    float s0 = (rr == 0) ? u0.x : (rr == 1) ? u0.y : (rr == 2) ? u0.z : u0.w;
                    float s1 = (rr == 0) ? u1.x : (rr == 1) ? u1.y : (rr == 2) ? u1.z : u1.w;
                    float s2 = (rr == 0) ? u2.x : (rr == 1) ? u2.y : (rr == 2) ? u2.z : u2.w;
                    float s3 = (rr == 0) ? u3.x : (rr == 1) ? u3.y : (rr == 2) ? u3.z : u3.w;
                    ull p0 = pack2(s0), p1 = pack2(s1), p2 = pack2(s2), p3 = pack2(s3);
                    acc[0][0] = ffma2(p0, kv.x, acc[0][0]); acc[0][1] = ffma2(p0, kv.y, acc[0][1]);
                    acc[1][0] = ffma2(p1, kv.x, acc[1][0]); acc[1][1] = ffma2(p1, kv.y, acc[1][1]);
                    acc[2][0] = ffma2(p2, kv.x, acc[2][0]); acc[2][1] = ffma2(p2, kv.y, acc[2][1]);
                    acc[3][0] = ffma2(p3, kv.x, acc[3][0]); acc[3][1] = ffma2(p3, kv.y, acc[3][1]);
                }
            }
            #pragma unroll
            for (int jj = 0; jj < 4; jj++) {
                ulonglong2* p = (ulonglong2*)&sm.St[warp + 4 * jj][c0];
                ulonglong2 v = *p;
                v.x = fadd2(v.x, acc[jj][0]);
                v.y = fadd2(v.y, acc[jj][1]);
                *p = v;
            }
        }
        // loop-top barrier separates C2's St / A's UAT writes from next reads
    }

    if (write_s) {
        __syncthreads();
        float* sf = sfinal + (size_t)bh * DIM * DIM + sl * DV;
        for (int idx = tid; idx < DIM * DV; idx += THR2) {
            int c = idx >> 4, jv = idx & 15;
            sf[(size_t)c * DIM + jv] = sm.St[jv][c];
        }
    }
}

// ============================================================
extern "C" void kernel_launch(void* const* d_in, const int* in_sizes, int n_in,
                              void* d_out, int out_size) {
    const float* q    = (const float*)d_in[0];
    const float* k    = (const float*)d_in[1];
    const float* v    = (const float*)d_in[2];
    const float* beta = (const float*)d_in[3];
    float* out = (float*)d_out;

    const int out_elems = BH * LSEQ * DIM;
    const int s_elems   = BH * DIM * DIM;
    int write_s = (out_size >= out_elems + s_elems) ? 1 : 0;
    float* sf = out + out_elems;

    static bool attr_done = false;
    if (!attr_done) {
        cudaFuncSetAttribute(k1_prepare, cudaFuncAttributeMaxDynamicSharedMemorySize,
                             (int)sizeof(SM1));
        cudaFuncSetAttribute(k2_scan, cudaFuncAttributeMaxDynamicSharedMemorySize,
                             (int)sizeof(SM2));
        attr_done = true;
    }

    dim3 g1(NCHUNK, BH);
    k1_prepare<<<g1, 256, sizeof(SM1)>>>(q, k, v, beta);

    dim3 g2(BH, NSLICE);
    k2_scan<<<g2, THR2, sizeof(SM2)>>>(out, sf, write_s);
}

// round 10
// speedup vs baseline: 1.5435x; 1.5435x over previous
#include <cuda_runtime.h>
#include <cstdint>

#define BH      16
#define LSEQ    4096
#define DIM     128
#define CHK     32
#define DV      16
#define NSLICE  8
#define NCHUNK  (LSEQ / CHK)
#define PD      132   // padded row length (floats), 528B, 16B-aligned
#define ATP     36    // Atb/UAT padded stride
#define THR2    512

typedef unsigned long long ull;

// ---- scratch (device globals; allocation-free) ----
__device__ float g_QN[(size_t)BH * LSEQ * DIM];
__device__ float g_KN[(size_t)BH * LSEQ * DIM];
__device__ float g_W [(size_t)BH * LSEQ * DIM];
__device__ float g_U [(size_t)BH * LSEQ * DIM];
__device__ float g_AT[(size_t)BH * NCHUNK * CHK * CHK];

// ---- packed f32x2 helpers ----
__device__ __forceinline__ ull ffma2(ull a, ull b, ull c) {
    ull d;
    asm("fma.rn.f32x2 %0, %1, %2, %3;" : "=l"(d) : "l"(a), "l"(b), "l"(c));
    return d;
}
__device__ __forceinline__ ull fadd2(ull a, ull b) {
    ull d;
    asm("add.rn.f32x2 %0, %1, %2;" : "=l"(d) : "l"(a), "l"(b));
    return d;
}
__device__ __forceinline__ ull pack2(float v) {
    ull d;
    asm("mov.b64 %0, {%1, %1};" : "=l"(d) : "f"(v));
    return d;
}
__device__ __forceinline__ float hadd2(ull v) {
    float lo, hi;
    asm("mov.b64 {%0, %1}, %2;" : "=f"(lo), "=f"(hi) : "l"(v));
    return lo + hi;
}

// ---- cp.async helpers ----
__device__ __forceinline__ void cp16(void* smem_dst, const void* gmem_src) {
    uint32_t s = (uint32_t)__cvta_generic_to_shared(smem_dst);
    asm volatile("cp.async.cg.shared.global [%0], [%1], 16;\n" :: "r"(s), "l"(gmem_src));
}
__device__ __forceinline__ void cp_commit() {
    asm volatile("cp.async.commit_group;\n" ::: "memory");
}
__device__ __forceinline__ void cp_wait_all() {
    asm volatile("cp.async.wait_group 0;\n" ::: "memory");
}

// ============================================================
// Kernel 1: per-(bh,chunk) prep; register-resident load+norm+scale
// ============================================================
struct SM1 {
    float Qn[CHK][PD];
    float Kn[CHK][PD];
    float Kb[CHK][PD];
    float Vb[CHK][PD];
    float T [CHK][CHK + 1];
};

extern "C" __global__ void __launch_bounds__(256)
k1_prepare(const float* __restrict__ q, const float* __restrict__ k,
           const float* __restrict__ v, const float* __restrict__ beta)
{
    extern __shared__ __align__(16) char smraw1[];
    SM1& sm = *reinterpret_cast<SM1*>(smraw1);
    const int ch = blockIdx.x, bh = blockIdx.y;
    const int tid = threadIdx.x;
    const size_t base = ((size_t)bh * LSEQ + (size_t)ch * CHK) * DIM;

    // ---- fused load + norm + scale: row r owned by 8 lanes ----
    {
        const int r = tid >> 3, sub = tid & 7;
        const float* qr = q + base + (size_t)r * DIM + sub * 16;
        const float* kr = k + base + (size_t)r * DIM + sub * 16;
        const float* vr = v + base + (size_t)r * DIM + sub * 16;
        float4 qv[4], kv[4], vv[4];
        #pragma unroll
        for (int g = 0; g < 4; g++) {
            qv[g] = *(const float4*)(qr + g * 4);
            kv[g] = *(const float4*)(kr + g * 4);
            vv[g] = *(const float4*)(vr + g * 4);
        }
        float sq = 0.f, sk = 0.f;
        #pragma unroll
        for (int g = 0; g < 4; g++) {
            sq += qv[g].x*qv[g].x + qv[g].y*qv[g].y + qv[g].z*qv[g].z + qv[g].w*qv[g].w;
            sk += kv[g].x*kv[g].x + kv[g].y*kv[g].y + kv[g].z*kv[g].z + kv[g].w*kv[g].w;
        }
        #pragma unroll
        for (int m = 4; m >= 1; m >>= 1) {
            sq += __shfl_xor_sync(0xffffffffu, sq, m);
            sk += __shfl_xor_sync(0xffffffffu, sk, m);
        }
        const float rq = rsqrtf(sq), rk = rsqrtf(sk);
        const float bt = beta[(size_t)bh * LSEQ + ch * CHK + r];

        float* gq = g_QN + base + (size_t)r * DIM + sub * 16;
        float* gk = g_KN + base + (size_t)r * DIM + sub * 16;
        #pragma unroll
        for (int g = 0; g < 4; g++) {
            float4 qn, kn, kb, vb;
            qn.x = qv[g].x*rq; qn.y = qv[g].y*rq; qn.z = qv[g].z*rq; qn.w = qv[g].w*rq;
            kn.x = kv[g].x*rk; kn.y = kv[g].y*rk; kn.z = kv[g].z*rk; kn.w = kv[g].w*rk;
            kb.x = kn.x*bt; kb.y = kn.y*bt; kb.z = kn.z*bt; kb.w = kn.w*bt;
            vb.x = vv[g].x*bt; vb.y = vv[g].y*bt; vb.z = vv[g].z*bt; vb.w = vv[g].w*bt;
            const int c = sub * 16 + g * 4;
            *(float4*)&sm.Qn[r][c] = qn;
            *(float4*)&sm.Kn[r][c] = kn;
            *(float4*)&sm.Kb[r][c] = kb;
            *(float4*)&sm.Vb[r][c] = vb;
            *(float4*)(gq + g * 4) = qn;
            *(float4*)(gk + g * 4) = kn;
        }
    }
    __syncthreads();

    { // T (strict lower, kb.kn) and At (causal, qn.kn), 2x2 tiles, f32x2 math
        int a = tid >> 4, b = tid & 15;
        int i0 = 2 * a, j0 = 2 * b;
        ull t00 = 0, t01 = 0, t10 = 0, t11 = 0;
        ull a00 = 0, a01 = 0, a10 = 0, a11 = 0;
        #pragma unroll 8
        for (int c4 = 0; c4 < DIM; c4 += 4) {
            ulonglong2 kb0 = *(const ulonglong2*)&sm.Kb[i0][c4];
            ulonglong2 kb1 = *(const ulonglong2*)&sm.Kb[i0 + 1][c4];
            ulonglong2 qn0 = *(const ulonglong2*)&sm.Qn[i0][c4];
            ulonglong2 qn1 = *(const ulonglong2*)&sm.Qn[i0 + 1][c4];
            ulonglong2 kn0 = *(const ulonglong2*)&sm.Kn[j0][c4];
            ulonglong2 kn1 = *(const ulonglong2*)&sm.Kn[j0 + 1][c4];
            t00 = ffma2(kb0.x, kn0.x, t00); t00 = ffma2(kb0.y, kn0.y, t00);
            t01 = ffma2(kb0.x, kn1.x, t01); t01 = ffma2(kb0.y, kn1.y, t01);
            t10 = ffma2(kb1.x, kn0.x, t10); t10 = ffma2(kb1.y, kn0.y, t10);
            t11 = ffma2(kb1.x, kn1.x, t11); t11 = ffma2(kb1.y, kn1.y, t11);
            a00 = ffma2(qn0.x, kn0.x, a00); a00 = ffma2(qn0.y, kn0.y, a00);
            a01 = ffma2(qn0.x, kn1.x, a01); a01 = ffma2(qn0.y, kn1.y, a01);
            a10 = ffma2(qn1.x, kn0.x, a10); a10 = ffma2(qn1.y, kn0.y, a10);
            a11 = ffma2(qn1.x, kn1.x, a11); a11 = ffma2(qn1.y, kn1.y, a11);
        }
        sm.T[i0][j0]         = (i0 > j0)         ? hadd2(t00) : 0.f;
        sm.T[i0][j0 + 1]     = (i0 > j0 + 1)     ? hadd2(t01) : 0.f;
        sm.T[i0 + 1][j0]     = (i0 + 1 > j0)     ? hadd2(t10) : 0.f;
        sm.T[i0 + 1][j0 + 1] = (i0 + 1 > j0 + 1) ? hadd2(t11) : 0.f;
        float* atg = g_AT + (size_t)(bh * NCHUNK + ch) * CHK * CHK;
        atg[i0 * CHK + j0]           = (i0 >= j0)         ? hadd2(a00) : 0.f;
        atg[i0 * CHK + j0 + 1]       = (i0 >= j0 + 1)     ? hadd2(a01) : 0.f;
        atg[(i0 + 1) * CHK + j0]     = (i0 + 1 >= j0)     ? hadd2(a10) : 0.f;
        atg[(i0 + 1) * CHK + j0 + 1] = (i0 + 1 >= j0 + 1) ? hadd2(a11) : 0.f;
    }
    __syncthreads();

    { // forward substitution: 256 threads = 256 rhs columns [kb | vb]
        const bool left = tid < DIM;
        const int col = left ? tid : tid - DIM;
        float x[CHK];
        #pragma unroll
        for (int i = 0; i < CHK; i++) x[i] = left ? sm.Kb[i][col] : sm.Vb[i][col];
        #pragma unroll
        for (int i = 1; i < CHK; i++) {
            float acc = x[i];
            #pragma unroll
            for (int m = 0; m < i; m++) acc -= sm.T[i][m] * x[m];
            x[i] = acc;
        }
        float* dst = (left ? g_W : g_U) + base + col;
        #pragma unroll
        for (int i = 0; i < CHK; i++) dst[(size_t)i * DIM] = x[i];
    }
}

// ============================================================
// Kernel 2: scan; A = 4i x 4j on warps 0-7 (conflict-free c-split),
//           C1 pair-tiled (warps 4-15) || C2 (warps 0-3)
// ============================================================
struct Buf {
    float Qn [CHK][PD];
    float Kn [CHK][PD];
    float Wv [CHK][PD];
    float Ub [CHK][DV];
    float Atb[CHK][ATP];
};
struct SM2 {
    float St  [DV][PD];     // S^T slice: [j][c]
    float UAT [DV][ATP];    // (u - w@S)^T: [j][i]
    float Obuf[CHK][17];    // q@S partials
    Buf   buf[2];
};

__device__ __forceinline__ void load_buf(Buf& B, int bh, int ch, int sl, int tid)
{
    const size_t base = ((size_t)bh * LSEQ + (size_t)ch * CHK) * DIM;
    const float* qs  = g_QN + base;
    const float* ks  = g_KN + base;
    const float* ws  = g_W  + base;
    const float* us  = g_U  + base + sl * DV;
    const float* ats = g_AT + (size_t)(bh * NCHUNK + ch) * CHK * CHK;

    #pragma unroll
    for (int t = tid; t < 1024; t += THR2) {
        int r = t >> 5, c4 = (t & 31) * 4;
        cp16(&B.Qn[r][c4], qs + r * DIM + c4);
        cp16(&B.Kn[r][c4], ks + r * DIM + c4);
        cp16(&B.Wv[r][c4], ws + r * DIM + c4);
    }
    if (tid < 128) {
        int r = tid >> 2, c4 = (tid & 3) * 4;
        cp16(&B.Ub[r][c4], us + r * DIM + c4);
    }
    if (tid < 256) {
        int r = tid >> 3, c4 = (tid & 7) * 4;
        cp16(&B.Atb[r][c4], ats + r * CHK + c4);
    }
}

extern "C" __global__ void __launch_bounds__(THR2, 1)
k2_scan(float* __restrict__ out, float* __restrict__ sfinal, int write_s)
{
    extern __shared__ __align__(16) char smraw2[];
    SM2& sm = *reinterpret_cast<SM2*>(smraw2);
    const int bh = blockIdx.x, sl = blockIdx.y;
    const int tid = threadIdx.x;
    const int warp = tid >> 5, lane = tid & 31;

    float* ob = out + (size_t)bh * LSEQ * DIM + sl * DV;

    for (int idx = tid; idx < DV * DIM; idx += THR2)
        sm.St[idx >> 7][idx & 127] = 0.f;

    load_buf(sm.buf[0], bh, 0, sl, tid);
    cp_commit();

    // phase A (warps 0..7): 32 tiles (8 i-groups x 4 j-groups), 8-way c-split
    // lane granule = csplit + 8*cc  -> 8 distinct 16B bank-groups per phase (cf)
    const int csplit = lane & 7;
    const int tileA  = warp * 4 + (lane >> 3);   // 0..31 for warp<8
    const int ia0 = (tileA & 7) * 4;
    const int ja0 = (tileA >> 3) * 4;

    // C2 ownership (warps 0..3): warp w -> js rows {w, w+4, w+8, w+12}
    const int c0 = lane * 4;

    for (int ch = 0; ch < NCHUNK; ch++) {
        cp_wait_all();
        __syncthreads();
        if (ch + 1 < NCHUNK) {
            load_buf(sm.buf[(ch + 1) & 1], bh, ch + 1, sl, tid);
            cp_commit();
        }
        const Buf& B = sm.buf[ch & 1];

        // ---- phase A: O = qn@S, A = w@S; 4i x 4j, conflict-free c-split ----
        if (warp < 8) {
            ull O2[4][4] = {}, A2[4][4] = {};
            #pragma unroll
            for (int cc = 0; cc < 4; cc++) {
                const int c4 = csplit * 4 + cc * 32;   // BANK-EXACT mapping
                ulonglong2 sv[4];
                #pragma unroll
                for (int jj = 0; jj < 4; jj++)
                    sv[jj] = *(const ulonglong2*)&sm.St[ja0 + jj][c4];
                #pragma unroll
                for (int ii = 0; ii < 4; ii++) {
                    ulonglong2 qv = *(const ulonglong2*)&B.Qn[ia0 + ii][c4];
                    ulonglong2 wv = *(const ulonglong2*)&B.Wv[ia0 + ii][c4];
                    #pragma unroll
                    for (int jj = 0; jj < 4; jj++) {
                        O2[ii][jj] = ffma2(qv.x, sv[jj].x, O2[ii][jj]);
                        O2[ii][jj] = ffma2(qv.y, sv[jj].y, O2[ii][jj]);
                        A2[ii][jj] = ffma2(wv.x, sv[jj].x, A2[ii][jj]);
                        A2[ii][jj] = ffma2(wv.y, sv[jj].y, A2[ii][jj]);
                    }
                }
            }
            float Ov[4][4], Av[4][4];
            #pragma unroll
            for (int ii = 0; ii < 4; ii++)
                #pragma unroll
                for (int jj = 0; jj < 4; jj++) {
                    Ov[ii][jj] = hadd2(O2[ii][jj]);
                    Av[ii][jj] = hadd2(A2[ii][jj]);
                }
            #pragma unroll
            for (int m = 4; m >= 1; m >>= 1) {
                #pragma unroll
                for (int ii = 0; ii < 4; ii++)
                    #pragma unroll
                    for (int jj = 0; jj < 4; jj++) {
                        Ov[ii][jj] += __shfl_xor_sync(0xffffffffu, Ov[ii][jj], m);
                        Av[ii][jj] += __shfl_xor_sync(0xffffffffu, Av[ii][jj], m);
                    }
            }
            if (csplit == 0) {
                #pragma unroll
                for (int ii = 0; ii < 4; ii++)
                    #pragma unroll
                    for (int jj = 0; jj < 4; jj++) {
                        sm.UAT[ja0 + jj][ia0 + ii] =
                            B.Ub[ia0 + ii][ja0 + jj] - Av[ii][jj];
                        sm.Obuf[ia0 + ii][ja0 + jj] = Ov[ii][jj];
                    }
            }
        }
        __syncthreads();

        if (warp >= 4) {
            // ---- C1 (warps 4..11 effective): pair (i,j) and (i,j+8) ----
            const int idx = tid - 128;               // 0..383
            if (idx < 256) {
                const int i1 = idx >> 3, j1 = idx & 7;
                ull oa = 0, obp = 0;
                #pragma unroll
                for (int f4 = 0; f4 < CHK; f4 += 4) {
                    ulonglong2 a2v = *(const ulonglong2*)&B.Atb[i1][f4];
                    ulonglong2 ua  = *(const ulonglong2*)&sm.UAT[j1][f4];
                    ulonglong2 ub2 = *(const ulonglong2*)&sm.UAT[j1 + 8][f4];
                    oa  = ffma2(a2v.x, ua.x,  oa);  oa  = ffma2(a2v.y, ua.y,  oa);
                    obp = ffma2(a2v.x, ub2.x, obp); obp = ffma2(a2v.y, ub2.y, obp);
                }
                float* orow = ob + (size_t)(ch * CHK + i1) * DIM;
                orow[j1]     = sm.Obuf[i1][j1]     + hadd2(oa);
                orow[j1 + 8] = sm.Obuf[i1][j1 + 8] + hadd2(obp);
            }
        } else {
            // ---- C2 (warps 0..3): St[js][c0..3] += sum_r UA[r][js]*kn[r][c] ----
            ull acc[4][2] = {};
            #pragma unroll
            for (int r0 = 0; r0 < CHK; r0 += 4) {
                float4 u0 = *(const float4*)&sm.UAT[warp     ][r0];
                float4 u1 = *(const float4*)&sm.UAT[warp + 4 ][r0];
                float4 u2 = *(const float4*)&sm.UAT[warp + 8 ][r0];
                float4 u3 = *(const float4*)&sm.UAT[warp + 12][r0];
                #pragma unroll
                for (int rr = 0; rr < 4; rr++) {
                    ulonglong2 kv = *(const ulonglong2*)&B.Kn[r0 + rr][c0];
                    float s0 = (rr == 0) ? u0.x : (rr == 1) ? u0.y : (rr == 2) ? u0.z : u0.w;
                    float s1 = (rr == 0) ? u1.x : (rr == 1) ? u1.y : (rr == 2) ? u1.z : u1.w;
                    float s2 = (rr == 0) ? u2.x : (rr == 1) ? u2.y : (rr == 2) ? u2.z : u2.w;
                    float s3 = (rr == 0) ? u3.x : (rr == 1) ? u3.y : (rr == 2) ? u3.z : u3.w;
                    ull p0 = pack2(s0), p1 = pack2(s1), p2 = pack2(s2), p3 = pack2(s3);
                    acc[0][0] = ffma2(p0, kv.x, acc[0][0]); acc[0][1] = ffma2(p0, kv.y, acc[0][1]);
                    acc[1][0] = ffma2(p1, kv.x, acc[1][0]); acc[1][1] = ffma2(p1, kv.y, acc[1][1]);
                    acc[2][0] = ffma2(p2, kv.x, acc[2][0]); acc[2][1] = ffma2(p2, kv.y, acc[2][1]);
                    acc[3][0] = ffma2(p3, kv.x, acc[3][0]); acc[3][1] = ffma2(p3, kv.y, acc[3][1]);
                }
            }
            #pragma unroll
            for (int jj = 0; jj < 4; jj++) {
                ulonglong2* p = (ulonglong2*)&sm.St[warp + 4 * jj][c0];
                ulonglong2 v = *p;
                v.x = fadd2(v.x, acc[jj][0]);
                v.y = fadd2(v.y, acc[jj][1]);
                *p = v;
            }
        }
        // loop-top barrier separates C2's St / A's UAT writes from next reads
    }

    if (write_s) {
        __syncthreads();
        float* sf = sfinal + (size_t)bh * DIM * DIM + sl * DV;
        for (int idx = tid; idx < DIM * DV; idx += THR2) {
            int c = idx >> 4, jv = idx & 15;
            sf[(size_t)c * DIM + jv] = sm.St[jv][c];
        }
    }
}

// ============================================================
extern "C" void kernel_launch(void* const* d_in, const int* in_sizes, int n_in,
                              void* d_out, int out_size) {
    const float* q    = (const float*)d_in[0];
    const float* k    = (const float*)d_in[1];
    const float* v    = (const float*)d_in[2];
    const float* beta = (const float*)d_in[3];
    float* out = (float*)d_out;

    const int out_elems = BH * LSEQ * DIM;
    const int s_elems   = BH * DIM * DIM;
    int write_s = (out_size >= out_elems + s_elems) ? 1 : 0;
    float* sf = out + out_elems;

    static bool attr_done = false;
    if (!attr_done) {
        cudaFuncSetAttribute(k1_prepare, cudaFuncAttributeMaxDynamicSharedMemorySize,
                             (int)sizeof(SM1));
        cudaFuncSetAttribute(k2_scan, cudaFuncAttributeMaxDynamicSharedMemorySize,
                             (int)sizeof(SM2));
        attr_done = true;
    }

    dim3 g1(NCHUNK, BH);
    k1_prepare<<<g1, 256, sizeof(SM1)>>>(q, k, v, beta);

    dim3 g2(BH, NSLICE);
    k2_scan<<<g2, THR2, sizeof(SM2)>>>(out, sf, write_s);
}

// round 13
// speedup vs baseline: 1.6136x; 1.0454x over previous
#include <cuda_runtime.h>
#include <cstdint>

#define BH      16
#define LSEQ    4096
#define DIM     128
#define CHK     32
#define DV      16
#define NSLICE  8
#define NCHUNK  (LSEQ / CHK)
#define PD      132   // padded row length (floats), 528B, 16B-aligned
#define ATP     36    // Atb/UAT padded stride
#define THR2    512

typedef unsigned long long ull;

// ---- scratch (device globals; allocation-free) ----
__device__ float g_QN[(size_t)BH * LSEQ * DIM];
__device__ float g_KN[(size_t)BH * LSEQ * DIM];
__device__ float g_W [(size_t)BH * LSEQ * DIM];
__device__ float g_U [(size_t)BH * LSEQ * DIM];
__device__ float g_AT[(size_t)BH * NCHUNK * CHK * CHK];

// ---- packed f32x2 helpers ----
__device__ __forceinline__ ull ffma2(ull a, ull b, ull c) {
    ull d;
    asm("fma.rn.f32x2 %0, %1, %2, %3;" : "=l"(d) : "l"(a), "l"(b), "l"(c));
    return d;
}
__device__ __forceinline__ ull fadd2(ull a, ull b) {
    ull d;
    asm("add.rn.f32x2 %0, %1, %2;" : "=l"(d) : "l"(a), "l"(b));
    return d;
}
__device__ __forceinline__ ull pack2(float v) {
    ull d;
    asm("mov.b64 %0, {%1, %1};" : "=l"(d) : "f"(v));
    return d;
}
__device__ __forceinline__ float hadd2(ull v) {
    float lo, hi;
    asm("mov.b64 {%0, %1}, %2;" : "=f"(lo), "=f"(hi) : "l"(v));
    return lo + hi;
}

// ---- cp.async helpers ----
__device__ __forceinline__ void cp16(void* smem_dst, const void* gmem_src) {
    uint32_t s = (uint32_t)__cvta_generic_to_shared(smem_dst);
    asm volatile("cp.async.cg.shared.global [%0], [%1], 16;\n" :: "r"(s), "l"(gmem_src));
}
__device__ __forceinline__ void cp_commit() {
    asm volatile("cp.async.commit_group;\n" ::: "memory");
}
__device__ __forceinline__ void cp_wait_all() {
    asm volatile("cp.async.wait_group 0;\n" ::: "memory");
}

// ============================================================
// Kernel 1: per-(bh,chunk) prep; register-resident load+norm+scale
// ============================================================
struct SM1 {
    float Qn[CHK][PD];
    float Kn[CHK][PD];
    float Kb[CHK][PD];
    float Vb[CHK][PD];
    float T [CHK][CHK + 1];
};

extern "C" __global__ void __launch_bounds__(256)
k1_prepare(const float* __restrict__ q, const float* __restrict__ k,
           const float* __restrict__ v, const float* __restrict__ beta)
{
    extern __shared__ __align__(16) char smraw1[];
    SM1& sm = *reinterpret_cast<SM1*>(smraw1);
    const int ch = blockIdx.x, bh = blockIdx.y;
    const int tid = threadIdx.x;
    const size_t base = ((size_t)bh * LSEQ + (size_t)ch * CHK) * DIM;

    // ---- fused load + norm + scale: row r owned by 8 lanes ----
    {
        const int r = tid >> 3, sub = tid & 7;
        const float* qr = q + base + (size_t)r * DIM + sub * 16;
        const float* kr = k + base + (size_t)r * DIM + sub * 16;
        const float* vr = v + base + (size_t)r * DIM + sub * 16;
        float4 qv[4], kv[4], vv[4];
        #pragma unroll
        for (int g = 0; g < 4; g++) {
            qv[g] = *(const float4*)(qr + g * 4);
            kv[g] = *(const float4*)(kr + g * 4);
            vv[g] = *(const float4*)(vr + g * 4);
        }
        float sq = 0.f, sk = 0.f;
        #pragma unroll
        for (int g = 0; g < 4; g++) {
            sq += qv[g].x*qv[g].x + qv[g].y*qv[g].y + qv[g].z*qv[g].z + qv[g].w*qv[g].w;
            sk += kv[g].x*kv[g].x + kv[g].y*kv[g].y + kv[g].z*kv[g].z + kv[g].w*kv[g].w;
        }
        #pragma unroll
        for (int m = 4; m >= 1; m >>= 1) {
            sq += __shfl_xor_sync(0xffffffffu, sq, m);
            sk += __shfl_xor_sync(0xffffffffu, sk, m);
        }
        const float rq = rsqrtf(sq), rk = rsqrtf(sk);
        const float bt = beta[(size_t)bh * LSEQ + ch * CHK + r];

        float* gq = g_QN + base + (size_t)r * DIM + sub * 16;
        float* gk = g_KN + base + (size_t)r * DIM + sub * 16;
        #pragma unroll
        for (int g = 0; g < 4; g++) {
            float4 qn, kn, kb, vb;
            qn.x = qv[g].x*rq; qn.y = qv[g].y*rq; qn.z = qv[g].z*rq; qn.w = qv[g].w*rq;
            kn.x = kv[g].x*rk; kn.y = kv[g].y*rk; kn.z = kv[g].z*rk; kn.w = kv[g].w*rk;
            kb.x = kn.x*bt; kb.y = kn.y*bt; kb.z = kn.z*bt; kb.w = kn.w*bt;
            vb.x = vv[g].x*bt; vb.y = vv[g].y*bt; vb.z = vv[g].z*bt; vb.w = vv[g].w*bt;
            const int c = sub * 16 + g * 4;
            *(float4*)&sm.Qn[r][c] = qn;
            *(float4*)&sm.Kn[r][c] = kn;
            *(float4*)&sm.Kb[r][c] = kb;
            *(float4*)&sm.Vb[r][c] = vb;
            *(float4*)(gq + g * 4) = qn;
            *(float4*)(gk + g * 4) = kn;
        }
    }
    __syncthreads();

    { // T (strict lower, kb.kn) and At (causal, qn.kn), 2x2 tiles, f32x2 math
        int a = tid >> 4, b = tid & 15;
        int i0 = 2 * a, j0 = 2 * b;
        ull t00 = 0, t01 = 0, t10 = 0, t11 = 0;
        ull a00 = 0, a01 = 0, a10 = 0, a11 = 0;
        #pragma unroll 8
        for (int c4 = 0; c4 < DIM; c4 += 4) {
            ulonglong2 kb0 = *(const ulonglong2*)&sm.Kb[i0][c4];
            ulonglong2 kb1 = *(const ulonglong2*)&sm.Kb[i0 + 1][c4];
            ulonglong2 qn0 = *(const ulonglong2*)&sm.Qn[i0][c4];
            ulonglong2 qn1 = *(const ulonglong2*)&sm.Qn[i0 + 1][c4];
            ulonglong2 kn0 = *(const ulonglong2*)&sm.Kn[j0][c4];
            ulonglong2 kn1 = *(const ulonglong2*)&sm.Kn[j0 + 1][c4];
            t00 = ffma2(kb0.x, kn0.x, t00); t00 = ffma2(kb0.y, kn0.y, t00);
            t01 = ffma2(kb0.x, kn1.x, t01); t01 = ffma2(kb0.y, kn1.y, t01);
            t10 = ffma2(kb1.x, kn0.x, t10); t10 = ffma2(kb1.y, kn0.y, t10);
            t11 = ffma2(kb1.x, kn1.x, t11); t11 = ffma2(kb1.y, kn1.y, t11);
            a00 = ffma2(qn0.x, kn0.x, a00); a00 = ffma2(qn0.y, kn0.y, a00);
            a01 = ffma2(qn0.x, kn1.x, a01); a01 = ffma2(qn0.y, kn1.y, a01);
            a10 = ffma2(qn1.x, kn0.x, a10); a10 = ffma2(qn1.y, kn0.y, a10);
            a11 = ffma2(qn1.x, kn1.x, a11); a11 = ffma2(qn1.y, kn1.y, a11);
        }
        sm.T[i0][j0]         = (i0 > j0)         ? hadd2(t00) : 0.f;
        sm.T[i0][j0 + 1]     = (i0 > j0 + 1)     ? hadd2(t01) : 0.f;
        sm.T[i0 + 1][j0]     = (i0 + 1 > j0)     ? hadd2(t10) : 0.f;
        sm.T[i0 + 1][j0 + 1] = (i0 + 1 > j0 + 1) ? hadd2(t11) : 0.f;
        float* atg = g_AT + (size_t)(bh * NCHUNK + ch) * CHK * CHK;
        atg[i0 * CHK + j0]           = (i0 >= j0)         ? hadd2(a00) : 0.f;
        atg[i0 * CHK + j0 + 1]       = (i0 >= j0 + 1)     ? hadd2(a01) : 0.f;
        atg[(i0 + 1) * CHK + j0]     = (i0 + 1 >= j0)     ? hadd2(a10) : 0.f;
        atg[(i0 + 1) * CHK + j0 + 1] = (i0 + 1 >= j0 + 1) ? hadd2(a11) : 0.f;
    }
    __syncthreads();

    { // forward substitution: 256 threads = 256 rhs columns [kb | vb]
        const bool left = tid < DIM;
        const int col = left ? tid : tid - DIM;
        float x[CHK];
        #pragma unroll
        for (int i = 0; i < CHK; i++) x[i] = left ? sm.Kb[i][col] : sm.Vb[i][col];
        #pragma unroll
        for (int i = 1; i < CHK; i++) {
            float acc = x[i];
            #pragma unroll
            for (int m = 0; m < i; m++) acc -= sm.T[i][m] * x[m];
            x[i] = acc;
        }
        float* dst = (left ? g_W : g_U) + base + col;
        #pragma unroll
        for (int i = 0; i < CHK; i++) dst[(size_t)i * DIM] = x[i];
    }
}

// ============================================================
// Kernel 2: pipelined scan.
//   warps 0-7 : A(ch) -> bar.sync(1,256) -> C2(ch) on warps 0-3
//   warps 8-15: C1(ch-1)  (UAT/Obuf double-buffered, Atb ring of 3)
// ============================================================
struct Buf {
    float Qn [CHK][PD];
    float Kn [CHK][PD];
    float Wv [CHK][PD];
    float Ub [CHK][DV];
};
struct SM2 {
    float St  [DV][PD];       // S^T slice
    float UAT [2][DV][ATP];   // (u - w@S)^T, parity ch&1
    float Obuf[2][CHK][17];   // q@S partials, parity ch&1
    float Atb [3][CHK][ATP];  // causal attn ring, index ch%3
    Buf   buf[2];
};

__device__ __forceinline__ void load_buf(Buf& B, float (*atb)[ATP],
                                         int bh, int ch, int sl, int tid)
{
    const size_t base = ((size_t)bh * LSEQ + (size_t)ch * CHK) * DIM;
    const float* qs  = g_QN + base;
    const float* ks  = g_KN + base;
    const float* ws  = g_W  + base;
    const float* us  = g_U  + base + sl * DV;
    const float* ats = g_AT + (size_t)(bh * NCHUNK + ch) * CHK * CHK;

    #pragma unroll
    for (int t = tid; t < 1024; t += THR2) {
        int r = t >> 5, c4 = (t & 31) * 4;
        cp16(&B.Qn[r][c4], qs + r * DIM + c4);
        cp16(&B.Kn[r][c4], ks + r * DIM + c4);
        cp16(&B.Wv[r][c4], ws + r * DIM + c4);
    }
    if (tid < 128) {
        int r = tid >> 2, c4 = (tid & 3) * 4;
        cp16(&B.Ub[r][c4], us + r * DIM + c4);
    }
    if (tid < 256) {
        int r = tid >> 3, c4 = (tid & 7) * 4;
        cp16(&atb[r][c4], ats + r * CHK + c4);
    }
}

extern "C" __global__ void __launch_bounds__(THR2, 1)
k2_scan(float* __restrict__ out, float* __restrict__ sfinal, int write_s)
{
    extern __shared__ __align__(16) char smraw2[];
    SM2& sm = *reinterpret_cast<SM2*>(smraw2);
    const int bh = blockIdx.x, sl = blockIdx.y;
    const int tid = threadIdx.x;
    const int warp = tid >> 5, lane = tid & 31;

    float* ob = out + (size_t)bh * LSEQ * DIM + sl * DV;

    for (int idx = tid; idx < DV * DIM; idx += THR2)
        sm.St[idx >> 7][idx & 127] = 0.f;

    load_buf(sm.buf[0], sm.Atb[0], bh, 0, sl, tid);
    cp_commit();

    // phase A (warps 0..7): 32 tiles (8 i-groups x 4 j-groups), 8-way c-split
    const int csplit = lane & 7;
    const int tileA  = warp * 4 + (lane >> 3);
    const int ia0 = (tileA & 7) * 4;
    const int ja0 = (tileA >> 3) * 4;

    // C2 (warps 0..3): warp w -> js rows {w, w+4, w+8, w+12}
    const int c0 = lane * 4;

    for (int ch = 0; ch < NCHUNK; ch++) {
        cp_wait_all();
        __syncthreads();
        if (ch + 1 < NCHUNK) {
            load_buf(sm.buf[(ch + 1) & 1], sm.Atb[(ch + 1) % 3], bh, ch + 1, sl, tid);
            cp_commit();
        }
        const Buf& B = sm.buf[ch & 1];
        const int p  = ch & 1;

        if (warp < 8) {
            // ---- phase A: O = qn@S, A = w@S; 4i x 4j, conflict-free c-split ----
            ull O2[4][4] = {}, A2[4][4] = {};
            #pragma unroll
            for (int cc = 0; cc < 4; cc++) {
                const int c4 = csplit * 4 + cc * 32;   // bank-exact mapping
                ulonglong2 sv[4];
                #pragma unroll
                for (int jj = 0; jj < 4; jj++)
                    sv[jj] = *(const ulonglong2*)&sm.St[ja0 + jj][c4];
                #pragma unroll
                for (int ii = 0; ii < 4; ii++) {
                    ulonglong2 qv = *(const ulonglong2*)&B.Qn[ia0 + ii][c4];
                    ulonglong2 wv = *(const ulonglong2*)&B.Wv[ia0 + ii][c4];
                    #pragma unroll
                    for (int jj = 0; jj < 4; jj++) {
                        O2[ii][jj] = ffma2(qv.x, sv[jj].x, O2[ii][jj]);
                        O2[ii][jj] = ffma2(qv.y, sv[jj].y, O2[ii][jj]);
                        A2[ii][jj] = ffma2(wv.x, sv[jj].x, A2[ii][jj]);
                        A2[ii][jj] = ffma2(wv.y, sv[jj].y, A2[ii][jj]);
                    }
                }
            }
            float Ov[4][4], Av[4][4];
            #pragma unroll
            for (int ii = 0; ii < 4; ii++)
                #pragma unroll
                for (int jj = 0; jj < 4; jj++) {
                    Ov[ii][jj] = hadd2(O2[ii][jj]);
                    Av[ii][jj] = hadd2(A2[ii][jj]);
                }
            #pragma unroll
            for (int m = 4; m >= 1; m >>= 1) {
                #pragma unroll
                for (int ii = 0; ii < 4; ii++)
                    #pragma unroll
                    for (int jj = 0; jj < 4; jj++) {
                        Ov[ii][jj] += __shfl_xor_sync(0xffffffffu, Ov[ii][jj], m);
                        Av[ii][jj] += __shfl_xor_sync(0xffffffffu, Av[ii][jj], m);
                    }
            }
            if (csplit == 0) {
                #pragma unroll
                for (int ii = 0; ii < 4; ii++)
                    #pragma unroll
                    for (int jj = 0; jj < 4; jj++) {
                        sm.UAT[p][ja0 + jj][ia0 + ii] =
                            B.Ub[ia0 + ii][ja0 + jj] - Av[ii][jj];
                        sm.Obuf[p][ia0 + ii][ja0 + jj] = Ov[ii][jj];
                    }
            }
            asm volatile("bar.sync 1, 256;" ::: "memory");

            if (warp < 4) {
                // ---- C2: St[js][c0..3] += sum_r UA[r][js]*kn[r][c] ----
                ull acc[4][2] = {};
                #pragma unroll
                for (int r0 = 0; r0 < CHK; r0 += 4) {
                    float4 u0 = *(const float4*)&sm.UAT[p][warp     ][r0];
                    float4 u1 = *(const float4*)&sm.UAT[p][warp + 4 ][r0];
                    float4 u2 = *(const float4*)&sm.UAT[p][warp + 8 ][r0];
                    float4 u3 = *(const float4*)&sm.UAT[p][warp + 12][r0];
                    #pragma unroll
                    for (int rr = 0; rr < 4; rr++) {
                        ulonglong2 kv = *(const ulonglong2*)&B.Kn[r0 + rr][c0];
                        float s0 = (rr == 0) ? u0.x : (rr == 1) ? u0.y : (rr == 2) ? u0.z : u0.w;
                        float s1 = (rr == 0) ? u1.x : (rr == 1) ? u1.y : (rr == 2) ? u1.z : u1.w;
                        float s2 = (rr == 0) ? u2.x : (rr == 1) ? u2.y : (rr == 2) ? u2.z : u2.w;
                        float s3 = (rr == 0) ? u3.x : (rr == 1) ? u3.y : (rr == 2) ? u3.z : u3.w;
                        ull p0 = pack2(s0), p1 = pack2(s1), p2 = pack2(s2), p3 = pack2(s3);
                        acc[0][0] = ffma2(p0, kv.x, acc[0][0]); acc[0][1] = ffma2(p0, kv.y, acc[0][1]);
                        acc[1][0] = ffma2(p1, kv.x, acc[1][0]); acc[1][1] = ffma2(p1, kv.y, acc[1][1]);
                        acc[2][0] = ffma2(p2, kv.x, acc[2][0]); acc[2][1] = ffma2(p2, kv.y, acc[2][1]);
                        acc[3][0] = ffma2(p3, kv.x, acc[3][0]); acc[3][1] = ffma2(p3, kv.y, acc[3][1]);
                    }
                }
                #pragma unroll
                for (int jj = 0; jj < 4; jj++) {
                    ulonglong2* pp = (ulonglong2*)&sm.St[warp + 4 * jj][c0];
                    ulonglong2 v = *pp;
                    v.x = fadd2(v.x, acc[jj][0]);
                    v.y = fadd2(v.y, acc[jj][1]);
                    *pp = v;
                }
            }
        } else if (ch > 0) {
            // ---- C1(ch-1) on warps 8..15: out = Obuf + At @ UA ----
            const int pm = (ch - 1) & 1;
            const float (*atb)[ATP] = sm.Atb[(ch - 1) % 3];
            const int idx = tid - 256;               // 0..255
            const int i1 = idx >> 3, j1 = idx & 7;
            ull oa = 0, obp = 0;
            #pragma unroll
            for (int f4 = 0; f4 < CHK; f4 += 4) {
                ulonglong2 a2v = *(const ulonglong2*)&atb[i1][f4];
                ulonglong2 ua  = *(const ulonglong2*)&sm.UAT[pm][j1][f4];
                ulonglong2 ub2 = *(const ulonglong2*)&sm.UAT[pm][j1 + 8][f4];
                oa  = ffma2(a2v.x, ua.x,  oa);  oa  = ffma2(a2v.y, ua.y,  oa);
                obp = ffma2(a2v.x, ub2.x, obp); obp = ffma2(a2v.y, ub2.y, obp);
            }
            float* orow = ob + (size_t)((ch - 1) * CHK + i1) * DIM;
            orow[j1]     = sm.Obuf[pm][i1][j1]     + hadd2(oa);
            orow[j1 + 8] = sm.Obuf[pm][i1][j1 + 8] + hadd2(obp);
        }
        // loop-top __syncthreads orders: C2 St writes -> next A;
        // A's UAT[p] -> C1 next iter; C1 done before UAT[p] reused (2 iters).
    }

    // ---- epilogue: C1 for the last chunk ----
    __syncthreads();
    if (tid < 256) {
        const int chl = NCHUNK - 1;
        const int pm = chl & 1;
        const float (*atb)[ATP] = sm.Atb[chl % 3];
        const int i1 = tid >> 3, j1 = tid & 7;
        ull oa = 0, obp = 0;
        #pragma unroll
        for (int f4 = 0; f4 < CHK; f4 += 4) {
            ulonglong2 a2v = *(const ulonglong2*)&atb[i1][f4];
            ulonglong2 ua  = *(const ulonglong2*)&sm.UAT[pm][j1][f4];
            ulonglong2 ub2 = *(const ulonglong2*)&sm.UAT[pm][j1 + 8][f4];
            oa  = ffma2(a2v.x, ua.x,  oa);  oa  = ffma2(a2v.y, ua.y,  oa);
            obp = ffma2(a2v.x, ub2.x, obp); obp = ffma2(a2v.y, ub2.y, obp);
        }
        float* orow = ob + (size_t)(chl * CHK + i1) * DIM;
        orow[j1]     = sm.Obuf[pm][i1][j1]     + hadd2(oa);
        orow[j1 + 8] = sm.Obuf[pm][i1][j1 + 8] + hadd2(obp);
    }

    if (write_s) {
        __syncthreads();
        float* sf = sfinal + (size_t)bh * DIM * DIM + sl * DV;
        for (int idx = tid; idx < DIM * DV; idx += THR2) {
            int c = idx >> 4, jv = idx & 15;
            sf[(size_t)c * DIM + jv] = sm.St[jv][c];
        }
    }
}

// ============================================================
extern "C" void kernel_launch(void* const* d_in, const int* in_sizes, int n_in,
                              void* d_out, int out_size) {
    const float* q    = (const float*)d_in[0];
    const float* k    = (const float*)d_in[1];
    const float* v    = (const float*)d_in[2];
    const float* beta = (const float*)d_in[3];
    float* out = (float*)d_out;

    const int out_elems = BH * LSEQ * DIM;
    const int s_elems   = BH * DIM * DIM;
    int write_s = (out_size >= out_elems + s_elems) ? 1 : 0;
    float* sf = out + out_elems;

    static bool attr_done = false;
    if (!attr_done) {
        cudaFuncSetAttribute(k1_prepare, cudaFuncAttributeMaxDynamicSharedMemorySize,
                             (int)sizeof(SM1));
        cudaFuncSetAttribute(k2_scan, cudaFuncAttributeMaxDynamicSharedMemorySize,
                             (int)sizeof(SM2));
        attr_done = true;
    }

    dim3 g1(NCHUNK, BH);
    k1_prepare<<<g1, 256, sizeof(SM1)>>>(q, k, v, beta);

    dim3 g2(BH, NSLICE);
    k2_scan<<<g2, THR2, sizeof(SM2)>>>(out, sf, write_s);
}

// round 15
// speedup vs baseline: 1.8869x; 1.1694x over previous
#include <cuda_runtime.h>
#include <cstdint>

#define BH      16
#define LSEQ    4096
#define DIM     128
#define CHK     32
#define DV      16
#define NSLICE  8
#define NCHUNK  (LSEQ / CHK)
#define PD      132   // padded row length (floats)
#define ATP     36    // Atb/UAT padded stride
#define TP      36    // T padded stride (k1)
#define OBP     20    // Obuf stride (80B, 16B-aligned rows)
#define THR2    512

typedef unsigned long long ull;

// ---- scratch (device globals; allocation-free) ----
__device__ float g_QN[(size_t)BH * LSEQ * DIM];
__device__ float g_KN[(size_t)BH * LSEQ * DIM];
__device__ float g_W [(size_t)BH * LSEQ * DIM];
__device__ float g_U [(size_t)BH * LSEQ * DIM];
__device__ float g_AT[(size_t)BH * NCHUNK * CHK * CHK];

// ---- packed f32x2 helpers ----
__device__ __forceinline__ ull ffma2(ull a, ull b, ull c) {
    ull d;
    asm("fma.rn.f32x2 %0, %1, %2, %3;" : "=l"(d) : "l"(a), "l"(b), "l"(c));
    return d;
}
__device__ __forceinline__ ull fadd2(ull a, ull b) {
    ull d;
    asm("add.rn.f32x2 %0, %1, %2;" : "=l"(d) : "l"(a), "l"(b));
    return d;
}
__device__ __forceinline__ ull fsub2(ull a, ull b) {
    ull d;
    asm("sub.rn.f32x2 %0, %1, %2;" : "=l"(d) : "l"(a), "l"(b));
    return d;
}
__device__ __forceinline__ ull pack2(float v) {
    ull d;
    asm("mov.b64 %0, {%1, %1};" : "=l"(d) : "f"(v));
    return d;
}
__device__ __forceinline__ ull packab(float a, float b) {
    ull d;
    asm("mov.b64 %0, {%1, %2};" : "=l"(d) : "f"(a), "f"(b));
    return d;
}
__device__ __forceinline__ float hadd2(ull v) {
    float lo, hi;
    asm("mov.b64 {%0, %1}, %2;" : "=f"(lo), "=f"(hi) : "l"(v));
    return lo + hi;
}
__device__ __forceinline__ void unpack2(ull v, float& lo, float& hi) {
    asm("mov.b64 {%0, %1}, %2;" : "=f"(lo), "=f"(hi) : "l"(v));
}

// ---- cp.async helpers ----
__device__ __forceinline__ void cp16(void* smem_dst, const void* gmem_src) {
    uint32_t s = (uint32_t)__cvta_generic_to_shared(smem_dst);
    asm volatile("cp.async.cg.shared.global [%0], [%1], 16;\n" :: "r"(s), "l"(gmem_src));
}
__device__ __forceinline__ void cp_commit() {
    asm volatile("cp.async.commit_group;\n" ::: "memory");
}
__device__ __forceinline__ void cp_wait_all() {
    asm volatile("cp.async.wait_group 0;\n" ::: "memory");
}

// ============================================================
// Kernel 1: per-(bh,chunk) prep
// ============================================================
struct SM1 {
    float Qn[CHK][PD];
    float Kn[CHK][PD];
    float Kb[CHK][PD];
    float Vb[CHK][PD];
    float T [CHK][TP];
};

extern "C" __global__ void __launch_bounds__(256)
k1_prepare(const float* __restrict__ q, const float* __restrict__ k,
           const float* __restrict__ v, const float* __restrict__ beta)
{
    extern __shared__ __align__(16) char smraw1[];
    SM1& sm = *reinterpret_cast<SM1*>(smraw1);
    const int ch = blockIdx.x, bh = blockIdx.y;
    const int tid = threadIdx.x, lane = tid & 31, warp = tid >> 5;
    const size_t base = ((size_t)bh * LSEQ + (size_t)ch * CHK) * DIM;

    // ---- fused load + norm + scale: row r owned by 8 lanes ----
    {
        const int r = tid >> 3, sub = tid & 7;
        const float* qr = q + base + (size_t)r * DIM + sub * 16;
        const float* kr = k + base + (size_t)r * DIM + sub * 16;
        const float* vr = v + base + (size_t)r * DIM + sub * 16;
        float4 qv[4], kv[4], vv[4];
        #pragma unroll
        for (int g = 0; g < 4; g++) {
            qv[g] = *(const float4*)(qr + g * 4);
            kv[g] = *(const float4*)(kr + g * 4);
            vv[g] = *(const float4*)(vr + g * 4);
        }
        float sq = 0.f, sk = 0.f;
        #pragma unroll
        for (int g = 0; g < 4; g++) {
            sq += qv[g].x*qv[g].x + qv[g].y*qv[g].y + qv[g].z*qv[g].z + qv[g].w*qv[g].w;
            sk += kv[g].x*kv[g].x + kv[g].y*kv[g].y + kv[g].z*kv[g].z + kv[g].w*kv[g].w;
        }
        #pragma unroll
        for (int m = 4; m >= 1; m >>= 1) {
            sq += __shfl_xor_sync(0xffffffffu, sq, m);
            sk += __shfl_xor_sync(0xffffffffu, sk, m);
        }
        const float rq = rsqrtf(sq), rk = rsqrtf(sk);
        const float bt = beta[(size_t)bh * LSEQ + ch * CHK + r];

        float* gq = g_QN + base + (size_t)r * DIM + sub * 16;
        float* gk = g_KN + base + (size_t)r * DIM + sub * 16;
        #pragma unroll
        for (int g = 0; g < 4; g++) {
            float4 qn, kn, kb, vb;
            qn.x = qv[g].x*rq; qn.y = qv[g].y*rq; qn.z = qv[g].z*rq; qn.w = qv[g].w*rq;
            kn.x = kv[g].x*rk; kn.y = kv[g].y*rk; kn.z = kv[g].z*rk; kn.w = kv[g].w*rk;
            kb.x = kn.x*bt; kb.y = kn.y*bt; kb.z = kn.z*bt; kb.w = kn.w*bt;
            vb.x = vv[g].x*bt; vb.y = vv[g].y*bt; vb.z = vv[g].z*bt; vb.w = vv[g].w*bt;
            const int c = sub * 16 + g * 4;
            *(float4*)&sm.Qn[r][c] = qn;
            *(float4*)&sm.Kn[r][c] = kn;
            *(float4*)&sm.Kb[r][c] = kb;
            *(float4*)&sm.Vb[r][c] = vb;
            *(float4*)(gq + g * 4) = qn;
            *(float4*)(gk + g * 4) = kn;
        }
    }
    __syncthreads();

    { // T (strict lower) and At (causal): 4i x 4j tiles, 4-way c-split
        const int csplit = lane & 3;
        const int t = warp * 8 + (lane >> 2);     // 0..63
        const int ia0 = (t & 7) * 4;
        const int ja0 = (t >> 3) * 4;
        ull T2[4][4] = {}, A2[4][4] = {};
        #pragma unroll
        for (int cc = 0; cc < 8; cc++) {
            const int c4 = csplit * 4 + cc * 16;  // bank-exact
            ulonglong2 knv[4];
            #pragma unroll
            for (int jj = 0; jj < 4; jj++)
                knv[jj] = *(const ulonglong2*)&sm.Kn[ja0 + jj][c4];
            #pragma unroll
            for (int ii = 0; ii < 4; ii++) {
                ulonglong2 kbv = *(const ulonglong2*)&sm.Kb[ia0 + ii][c4];
                ulonglong2 qnv = *(const ulonglong2*)&sm.Qn[ia0 + ii][c4];
                #pragma unroll
                for (int jj = 0; jj < 4; jj++) {
                    T2[ii][jj] = ffma2(kbv.x, knv[jj].x, T2[ii][jj]);
                    T2[ii][jj] = ffma2(kbv.y, knv[jj].y, T2[ii][jj]);
                    A2[ii][jj] = ffma2(qnv.x, knv[jj].x, A2[ii][jj]);
                    A2[ii][jj] = ffma2(qnv.y, knv[jj].y, A2[ii][jj]);
                }
            }
        }
        float vv[32];
        #pragma unroll
        for (int ii = 0; ii < 4; ii++)
            #pragma unroll
            for (int jj = 0; jj < 4; jj++) {
                vv[ii * 4 + jj]      = hadd2(T2[ii][jj]);
                vv[16 + ii * 4 + jj] = hadd2(A2[ii][jj]);
            }
        // reduce-scatter: 2 rounds over csplit bits (1, 0); final vid = 8*csplit + k
        float t16[16];
        #pragma unroll
        for (int kk = 0; kk < 16; kk++) {
            float send = (csplit & 2) ? vv[kk] : vv[16 + kk];
            float recv = __shfl_xor_sync(0xffffffffu, send, 2);
            t16[kk] = ((csplit & 2) ? vv[16 + kk] : vv[kk]) + recv;
        }
        float t8[8];
        #pragma unroll
        for (int kk = 0; kk < 8; kk++) {
            float send = (csplit & 1) ? t16[kk] : t16[8 + kk];
            float recv = __shfl_xor_sync(0xffffffffu, send, 1);
            t8[kk] = ((csplit & 1) ? t16[8 + kk] : t16[kk]) + recv;
        }
        float* atg = g_AT + (size_t)(bh * NCHUNK + ch) * CHK * CHK;
        if (csplit < 2) {
            #pragma unroll
            for (int kk = 0; kk < 8; kk++) {
                int vid = 8 * csplit + kk;
                int gi = ia0 + (vid >> 2), gj = ja0 + (vid & 3);
                if (gi > gj) sm.T[gi][gj] = t8[kk];
            }
        } else {
            #pragma unroll
            for (int kk = 0; kk < 8; kk++) {
                int vid = 8 * csplit + kk - 16;
                int gi = ia0 + (vid >> 2), gj = ja0 + (vid & 3);
                atg[gi * CHK + gj] = (gi >= gj) ? t8[kk] : 0.f;
            }
        }
    }
    __syncthreads();

    // ---- forward substitution: 128 threads x 2 packed columns (kb | vb) ----
    if (tid < 128) {
        const int col = tid;
        ull x2[CHK];
        #pragma unroll
        for (int i = 0; i < CHK; i++)
            x2[i] = packab(sm.Kb[i][col], sm.Vb[i][col]);
        #pragma unroll
        for (int i = 1; i < CHK; i++) {
            ull acc = 0;
            #pragma unroll
            for (int m = 0; m < i; m++)
                acc = ffma2(pack2(sm.T[i][m]), x2[m], acc);
            x2[i] = fsub2(x2[i], acc);
        }
        float* dw = g_W + base + col;
        float* du = g_U + base + col;
        #pragma unroll
        for (int i = 0; i < CHK; i++) {
            float lo, hi;
            unpack2(x2[i], lo, hi);
            dw[(size_t)i * DIM] = lo;
            du[(size_t)i * DIM] = hi;
        }
    }
}

// ============================================================
// Kernel 2: pipelined scan.
//   warps 0-7 : A(ch) -> bar.sync(1,256) -> C2(ch) on warps 0-3
//   warps 8-11: C1(ch-1), 2i x 2j tiles (At/UAT read once per 4 cells)
// ============================================================
struct Buf {
    float Qn [CHK][PD];
    float Kn [CHK][PD];
    float Wv [CHK][PD];
    float Ub [CHK][DV];
};
struct SM2 {
    float St  [DV][PD];       // S^T slice
    float UAT [2][DV][ATP];   // (u - w@S)^T, parity ch&1
    float Obuf[2][CHK][OBP];  // q@S partials, parity ch&1
    float Atb [3][CHK][ATP];  // causal attn ring, index ch%3
    Buf   buf[2];
};

__device__ __forceinline__ void load_buf(Buf& B, float (*atb)[ATP],
                                         int bh, int ch, int sl, int tid)
{
    const size_t base = ((size_t)bh * LSEQ + (size_t)ch * CHK) * DIM;
    const float* qs  = g_QN + base;
    const float* ks  = g_KN + base;
    const float* ws  = g_W  + base;
    const float* us  = g_U  + base + sl * DV;
    const float* ats = g_AT + (size_t)(bh * NCHUNK + ch) * CHK * CHK;

    #pragma unroll
    for (int t = tid; t < 1024; t += THR2) {
        int r = t >> 5, c4 = (t & 31) * 4;
        cp16(&B.Qn[r][c4], qs + r * DIM + c4);
        cp16(&B.Kn[r][c4], ks + r * DIM + c4);
        cp16(&B.Wv[r][c4], ws + r * DIM + c4);
    }
    if (tid < 128) {
        int r = tid >> 2, c4 = (tid & 3) * 4;
        cp16(&B.Ub[r][c4], us + r * DIM + c4);
    }
    if (tid < 256) {
        int r = tid >> 3, c4 = (tid & 7) * 4;
        cp16(&atb[r][c4], ats + r * CHK + c4);
    }
}

extern "C" __global__ void __launch_bounds__(THR2, 1)
k2_scan(float* __restrict__ out, float* __restrict__ sfinal, int write_s)
{
    extern __shared__ __align__(16) char smraw2[];
    SM2& sm = *reinterpret_cast<SM2*>(smraw2);
    const int bh = blockIdx.x, sl = blockIdx.y;
    const int tid = threadIdx.x;
    const int warp = tid >> 5, lane = tid & 31;

    float* ob = out + (size_t)bh * LSEQ * DIM + sl * DV;

    for (int idx = tid; idx < DV * DIM; idx += THR2)
        sm.St[idx >> 7][idx & 127] = 0.f;

    load_buf(sm.buf[0], sm.Atb[0], bh, 0, sl, tid);
    cp_commit();

    // phase A (warps 0..7): 32 tiles (8 ig x 4 jg), 8-way c-split
    const int csplit = lane & 7;
    const int tileA  = warp * 4 + (lane >> 3);
    const int ia0 = (tileA & 7) * 4;
    const int ja0 = (tileA >> 3) * 4;

    // C2 (warps 0..3): warp w -> js rows {w, w+4, w+8, w+12}
    const int c0 = lane * 4;

    for (int ch = 0; ch < NCHUNK; ch++) {
        cp_wait_all();
        __syncthreads();
        if (ch + 1 < NCHUNK) {
            load_buf(sm.buf[(ch + 1) & 1], sm.Atb[(ch + 1) % 3], bh, ch + 1, sl, tid);
            cp_commit();
        }
        const Buf& B = sm.buf[ch & 1];
        const int p  = ch & 1;

        if (warp < 8) {
            // ---- phase A: O = qn@S, A = w@S; 4i x 4j, conflict-free c-split ----
            ull O2[4][4] = {}, A2[4][4] = {};
            #pragma unroll
            for (int cc = 0; cc < 4; cc++) {
                const int c4 = csplit * 4 + cc * 32;   // bank-exact
                ulonglong2 sv[4];
                #pragma unroll
                for (int jj = 0; jj < 4; jj++)
                    sv[jj] = *(const ulonglong2*)&sm.St[ja0 + jj][c4];
                #pragma unroll
                for (int ii = 0; ii < 4; ii++) {
                    ulonglong2 qv = *(const ulonglong2*)&B.Qn[ia0 + ii][c4];
                    ulonglong2 wv = *(const ulonglong2*)&B.Wv[ia0 + ii][c4];
                    #pragma unroll
                    for (int jj = 0; jj < 4; jj++) {
                        O2[ii][jj] = ffma2(qv.x, sv[jj].x, O2[ii][jj]);
                        O2[ii][jj] = ffma2(qv.y, sv[jj].y, O2[ii][jj]);
                        A2[ii][jj] = ffma2(wv.x, sv[jj].x, A2[ii][jj]);
                        A2[ii][jj] = ffma2(wv.y, sv[jj].y, A2[ii][jj]);
                    }
                }
            }
            float vv[32];
            #pragma unroll
            for (int ii = 0; ii < 4; ii++)
                #pragma unroll
                for (int jj = 0; jj < 4; jj++) {
                    vv[ii * 4 + jj]      = hadd2(O2[ii][jj]);
                    vv[16 + ii * 4 + jj] = hadd2(A2[ii][jj]);
                }
            // reduce-scatter over csplit bits (2,1,0); final vid = 4*csplit + k
            float t16[16];
            #pragma unroll
            for (int kk = 0; kk < 16; kk++) {
                float send = (csplit & 4) ? vv[kk] : vv[16 + kk];
                float recv = __shfl_xor_sync(0xffffffffu, send, 4);
                t16[kk] = ((csplit & 4) ? vv[16 + kk] : vv[kk]) + recv;
            }
            float t8[8];
            #pragma unroll
            for (int kk = 0; kk < 8; kk++) {
                float send = (csplit & 2) ? t16[kk] : t16[8 + kk];
                float recv = __shfl_xor_sync(0xffffffffu, send, 2);
                t8[kk] = ((csplit & 2) ? t16[8 + kk] : t16[kk]) + recv;
            }
            float t4[4];
            #pragma unroll
            for (int kk = 0; kk < 4; kk++) {
                float send = (csplit & 1) ? t8[kk] : t8[4 + kk];
                float recv = __shfl_xor_sync(0xffffffffu, send, 1);
                t4[kk] = ((csplit & 1) ? t8[4 + kk] : t8[kk]) + recv;
            }
            if (csplit < 4) {
                // O values: ii = csplit, jj = k
                *(float4*)&sm.Obuf[p][ia0 + csplit][ja0] =
                    make_float4(t4[0], t4[1], t4[2], t4[3]);
            } else {
                const int ii = csplit - 4;
                float4 ub = *(const float4*)&B.Ub[ia0 + ii][ja0];
                sm.UAT[p][ja0 + 0][ia0 + ii] = ub.x - t4[0];
                sm.UAT[p][ja0 + 1][ia0 + ii] = ub.y - t4[1];
                sm.UAT[p][ja0 + 2][ia0 + ii] = ub.z - t4[2];
                sm.UAT[p][ja0 + 3][ia0 + ii] = ub.w - t4[3];
            }
            asm volatile("bar.sync 1, 256;" ::: "memory");

            if (warp < 4) {
                // ---- C2: St[js][c0..3] += sum_r UA[r][js]*kn[r][c] ----
                ull acc[4][2] = {};
                #pragma unroll
                for (int r0 = 0; r0 < CHK; r0 += 4) {
                    float4 u0 = *(const float4*)&sm.UAT[p][warp     ][r0];
                    float4 u1 = *(const float4*)&sm.UAT[p][warp + 4 ][r0];
                    float4 u2 = *(const float4*)&sm.UAT[p][warp + 8 ][r0];
                    float4 u3 = *(const float4*)&sm.UAT[p][warp + 12][r0];
                    #pragma unroll
                    for (int rr = 0; rr < 4; rr++) {
                        ulonglong2 kv = *(const ulonglong2*)&B.Kn[r0 + rr][c0];
                        float s0 = (rr == 0) ? u0.x : (rr == 1) ? u0.y : (rr == 2) ? u0.z : u0.w;
                        float s1 = (rr == 0) ? u1.x : (rr == 1) ? u1.y : (rr == 2) ? u1.z : u1.w;
                        float s2 = (rr == 0) ? u2.x : (rr == 1) ? u2.y : (rr == 2) ? u2.z : u2.w;
                        float s3 = (rr == 0) ? u3.x : (rr == 1) ? u3.y : (rr == 2) ? u3.z : u3.w;
                        ull p0 = pack2(s0), p1 = pack2(s1), p2 = pack2(s2), p3 = pack2(s3);
                        acc[0][0] = ffma2(p0, kv.x, acc[0][0]); acc[0][1] = ffma2(p0, kv.y, acc[0][1]);
                        acc[1][0] = ffma2(p1, kv.x, acc[1][0]); acc[1][1] = ffma2(p1, kv.y, acc[1][1]);
                        acc[2][0] = ffma2(p2, kv.x, acc[2][0]); acc[2][1] = ffma2(p2, kv.y, acc[2][1]);
                        acc[3][0] = ffma2(p3, kv.x, acc[3][0]); acc[3][1] = ffma2(p3, kv.y, acc[3][1]);
                    }
                }
                #pragma unroll
                for (int jj = 0; jj < 4; jj++) {
                    ulonglong2* pp = (ulonglong2*)&sm.St[warp + 4 * jj][c0];
                    ulonglong2 v = *pp;
                    v.x = fadd2(v.x, acc[jj][0]);
                    v.y = fadd2(v.y, acc[jj][1]);
                    *pp = v;
                }
            }
        } else if (ch > 0 && warp < 12) {
            // ---- C1(ch-1) on warps 8..11: 2i x 2j tiles ----
            const int pm = (ch - 1) & 1;
            const float (*atb)[ATP] = sm.Atb[(ch - 1) % 3];
            const int idx = tid - 256;               // 0..127
            const int a = idx >> 3;                  // rows 2a, 2a+1
            const int b = idx & 7;                   // cols b, b+8
            ull o00 = 0, o01 = 0, o10 = 0, o11 = 0;
            #pragma unroll
            for (int f4 = 0; f4 < CHK; f4 += 4) {
                ulonglong2 at0 = *(const ulonglong2*)&atb[2 * a][f4];
                ulonglong2 at1 = *(const ulonglong2*)&atb[2 * a + 1][f4];
                ulonglong2 u0  = *(const ulonglong2*)&sm.UAT[pm][b][f4];
                ulonglong2 u1  = *(const ulonglong2*)&sm.UAT[pm][b + 8][f4];
                o00 = ffma2(at0.x, u0.x, o00); o00 = ffma2(at0.y, u0.y, o00);
                o01 = ffma2(at0.x, u1.x, o01); o01 = ffma2(at0.y, u1.y, o01);
                o10 = ffma2(at1.x, u0.x, o10); o10 = ffma2(at1.y, u0.y, o10);
                o11 = ffma2(at1.x, u1.x, o11); o11 = ffma2(at1.y, u1.y, o11);
            }
            float* orow0 = ob + (size_t)((ch - 1) * CHK + 2 * a) * DIM;
            float* orow1 = orow0 + DIM;
            orow0[b]     = sm.Obuf[pm][2 * a][b]         + hadd2(o00);
            orow0[b + 8] = sm.Obuf[pm][2 * a][b + 8]     + hadd2(o01);
            orow1[b]     = sm.Obuf[pm][2 * a + 1][b]     + hadd2(o10);
            orow1[b + 8] = sm.Obuf[pm][2 * a + 1][b + 8] + hadd2(o11);
        }
        // loop-top __syncthreads orders: C2 St writes -> next A;
        // A's UAT[p] -> C1 next iter; UAT[p] reuse 2 iters away.
    }

    // ---- epilogue: C1 for the last chunk ----
    __syncthreads();
    if (tid < 128) {
        const int chl = NCHUNK - 1;
        const int pm = chl & 1;
        const float (*atb)[ATP] = sm.Atb[chl % 3];
        const int a = tid >> 3, b = tid & 7;
        ull o00 = 0, o01 = 0, o10 = 0, o11 = 0;
        #pragma unroll
        for (int f4 = 0; f4 < CHK; f4 += 4) {
            ulonglong2 at0 = *(const ulonglong2*)&atb[2 * a][f4];
            ulonglong2 at1 = *(const ulonglong2*)&atb[2 * a + 1][f4];
            ulonglong2 u0  = *(const ulonglong2*)&sm.UAT[pm][b][f4];
            ulonglong2 u1  = *(const ulonglong2*)&sm.UAT[pm][b + 8][f4];
            o00 = ffma2(at0.x, u0.x, o00); o00 = ffma2(at0.y, u0.y, o00);
            o01 = ffma2(at0.x, u1.x, o01); o01 = ffma2(at0.y, u1.y, o01);
            o10 = ffma2(at1.x, u0.x, o10); o10 = ffma2(at1.y, u0.y, o10);
            o11 = ffma2(at1.x, u1.x, o11); o11 = ffma2(at1.y, u1.y, o11);
        }
        float* orow0 = ob + (size_t)(chl * CHK + 2 * a) * DIM;
        float* orow1 = orow0 + DIM;
        orow0[b]     = sm.Obuf[pm][2 * a][b]         + hadd2(o00);
        orow0[b + 8] = sm.Obuf[pm][2 * a][b + 8]     + hadd2(o01);
        orow1[b]     = sm.Obuf[pm][2 * a + 1][b]     + hadd2(o10);
        orow1[b + 8] = sm.Obuf[pm][2 * a + 1][b + 8] + hadd2(o11);
    }

    if (write_s) {
        __syncthreads();
        float* sf = sfinal + (size_t)bh * DIM * DIM + sl * DV;
        for (int idx = tid; idx < DIM * DV; idx += THR2) {
            int c = idx >> 4, jv = idx & 15;
            sf[(size_t)c * DIM + jv] = sm.St[jv][c];
        }
    }
}

// ============================================================
extern "C" void kernel_launch(void* const* d_in, const int* in_sizes, int n_in,
                              void* d_out, int out_size) {
    const float* q    = (const float*)d_in[0];
    const float* k    = (const float*)d_in[1];
    const float* v    = (const float*)d_in[2];
    const float* beta = (const float*)d_in[3];
    float* out = (float*)d_out;

    const int out_elems = BH * LSEQ * DIM;
    const int s_elems   = BH * DIM * DIM;
    int write_s = (out_size >= out_elems + s_elems) ? 1 : 0;
    float* sf = out + out_elems;

    static bool attr_done = false;
    if (!attr_done) {
        cudaFuncSetAttribute(k1_prepare, cudaFuncAttributeMaxDynamicSharedMemorySize,
                             (int)sizeof(SM1));
        cudaFuncSetAttribute(k2_scan, cudaFuncAttributeMaxDynamicSharedMemorySize,
                             (int)sizeof(SM2));
        attr_done = true;
    }

    dim3 g1(NCHUNK, BH);
    k1_prepare<<<g1, 256, sizeof(SM1)>>>(q, k, v, beta);

    dim3 g2(BH, NSLICE);
    k2_scan<<<g2, THR2, sizeof(SM2)>>>(out, sf, write_s);
}